// round 1
// baseline (speedup 1.0000x reference)
#include <cuda_runtime.h>
#include <cstdint>

#define S_TOK 8192
#define D_DIM 2048
#define E_EXP 64
#define CAP   128

// ---------------- scratch (no allocations allowed) ----------------
__device__ float g_logits[S_TOK * E_EXP];          // 2 MB
__device__ int   g_idx[S_TOK];
__device__ float g_gate1[S_TOK];
__device__ int   g_loc[S_TOK];
__device__ float g_partialGateSum[512 * E_EXP];    // per-warp softmax sums
__device__ int   g_cnt[E_EXP];                     // pre-drop per-expert counts

// ---------------- GEMM: logits = x @ wg^T (fp32) ----------------
// BM=64 tokens, BN=64 experts (all), BK=32. 128 blocks x 128 threads.
// Thread tile 8 tokens x 4 experts = 32 accumulators -> FFMA-bound.
#define BM 64
#define BN 64
#define BK 32
#define SPAD 4  // smem row stride 68 floats: 16B-aligned float4 reads, bounded conflicts

__global__ void __launch_bounds__(128) gemm_kernel(const float* __restrict__ x,
                                                   const float* __restrict__ wg) {
    __shared__ float Xs[BK][BM + SPAD];
    __shared__ float Ws[BK][BN + SPAD];

    const int tid = threadIdx.x;
    const int m0  = blockIdx.x * BM;
    const int tx  = tid & 15;   // expert group: experts tx*4 .. tx*4+3
    const int ty  = tid >> 4;   // token group : tokens ty*8 .. ty*8+7

    int rowi[4], c4i[4];
#pragma unroll
    for (int i = 0; i < 4; i++) {
        int f = tid + i * 128;  // 512 float4 per tile
        rowi[i] = f >> 3;       // 8 float4 per 32-float row
        c4i[i]  = f & 7;
    }

    float4 xr[4], wr[4];
#pragma unroll
    for (int i = 0; i < 4; i++) {
        xr[i] = *(const float4*)(x  + (size_t)(m0 + rowi[i]) * D_DIM + c4i[i] * 4);
        wr[i] = *(const float4*)(wg + (size_t)rowi[i] * D_DIM + c4i[i] * 4);
    }

    float acc[8][4];
#pragma unroll
    for (int i = 0; i < 8; i++)
#pragma unroll
        for (int j = 0; j < 4; j++) acc[i][j] = 0.0f;

    const int NT = D_DIM / BK;  // 64 k-tiles
    for (int kt = 0; kt < NT; kt++) {
        // store prefetched tile (transposed: [k][m], [k][e])
#pragma unroll
        for (int i = 0; i < 4; i++) {
            int c = c4i[i] * 4, r = rowi[i];
            Xs[c + 0][r] = xr[i].x; Xs[c + 1][r] = xr[i].y;
            Xs[c + 2][r] = xr[i].z; Xs[c + 3][r] = xr[i].w;
            Ws[c + 0][r] = wr[i].x; Ws[c + 1][r] = wr[i].y;
            Ws[c + 2][r] = wr[i].z; Ws[c + 3][r] = wr[i].w;
        }
        __syncthreads();

        if (kt + 1 < NT) {  // prefetch next tile into registers (overlaps compute)
            int k0 = (kt + 1) * BK;
#pragma unroll
            for (int i = 0; i < 4; i++) {
                xr[i] = *(const float4*)(x  + (size_t)(m0 + rowi[i]) * D_DIM + k0 + c4i[i] * 4);
                wr[i] = *(const float4*)(wg + (size_t)rowi[i] * D_DIM + k0 + c4i[i] * 4);
            }
        }

#pragma unroll
        for (int k = 0; k < BK; k++) {
            float4 a0 = *(const float4*)&Xs[k][ty * 8];
            float4 a1 = *(const float4*)&Xs[k][ty * 8 + 4];
            float4 b  = *(const float4*)&Ws[k][tx * 4];
            float a[8] = {a0.x, a0.y, a0.z, a0.w, a1.x, a1.y, a1.z, a1.w};
            float bb[4] = {b.x, b.y, b.z, b.w};
#pragma unroll
            for (int i = 0; i < 8; i++)
#pragma unroll
                for (int j = 0; j < 4; j++) acc[i][j] = fmaf(a[i], bb[j], acc[i][j]);
        }
        __syncthreads();
    }

#pragma unroll
    for (int i = 0; i < 8; i++) {
        float4 v = make_float4(acc[i][0], acc[i][1], acc[i][2], acc[i][3]);
        *(float4*)&g_logits[(size_t)(m0 + ty * 8 + i) * E_EXP + tx * 4] = v;
    }
}

// ---------------- softmax + argmax (warp per token, 2 experts/lane) ----------------
__global__ void softmax_kernel() {
    const int gwarp = (blockIdx.x * blockDim.x + threadIdx.x) >> 5;  // 0..511
    const int lane  = threadIdx.x & 31;
    float acc0 = 0.0f, acc1 = 0.0f;

    for (int s = gwarp; s < S_TOK; s += 512) {
        float l0 = g_logits[(size_t)s * E_EXP + lane];
        float l1 = g_logits[(size_t)s * E_EXP + lane + 32];
        // argmax with first-occurrence tie-break (matches jnp.argmax)
        float mv; int mi;
        if (l0 >= l1) { mv = l0; mi = lane; } else { mv = l1; mi = lane + 32; }
#pragma unroll
        for (int off = 16; off; off >>= 1) {
            float ov = __shfl_down_sync(0xffffffffu, mv, off);
            int   oi = __shfl_down_sync(0xffffffffu, mi, off);
            if (ov > mv || (ov == mv && oi < mi)) { mv = ov; mi = oi; }
        }
        mv = __shfl_sync(0xffffffffu, mv, 0);
        mi = __shfl_sync(0xffffffffu, mi, 0);

        float e0 = expf(l0 - mv), e1 = expf(l1 - mv);
        float sum = e0 + e1;
#pragma unroll
        for (int off = 16; off; off >>= 1) sum += __shfl_down_sync(0xffffffffu, sum, off);
        sum = __shfl_sync(0xffffffffu, sum, 0);
        float inv = 1.0f / sum;

        acc0 += e0 * inv;
        acc1 += e1 * inv;
        if (lane == 0) { g_idx[s] = mi; g_gate1[s] = inv; }  // gates[argmax] = 1/sum
    }
    g_partialGateSum[(size_t)gwarp * E_EXP + lane]      = acc0;
    g_partialGateSum[(size_t)gwarp * E_EXP + lane + 32] = acc1;
}

// ---------------- ordered per-expert rank (cumsum of one-hot), single block ----------------
__global__ void __launch_bounds__(1024) scan_kernel() {
    __shared__ int warpCnt[32 * E_EXP];  // per-warp histogram -> turned into prefix base
    __shared__ int runBase[E_EXP];
    const int tid = threadIdx.x, lane = tid & 31, w = tid >> 5;
    if (tid < E_EXP) runBase[tid] = 0;
    __syncthreads();

    for (int chunk = 0; chunk < S_TOK / 1024; chunk++) {
        const int s = chunk * 1024 + tid;
        const int e = g_idx[s];
        unsigned mask = __match_any_sync(0xffffffffu, e);
        int rank = __popc(mask & ((1u << lane) - 1u));

        warpCnt[tid] = 0; warpCnt[tid + 1024] = 0;
        __syncthreads();
        if (rank == 0) warpCnt[w * E_EXP + e] = __popc(mask);  // leader writes count
        __syncthreads();
        if (tid < E_EXP) {  // serial prefix over 32 warps for this expert
            int running = runBase[tid];
            for (int ww = 0; ww < 32; ww++) {
                int c = warpCnt[ww * E_EXP + tid];
                warpCnt[ww * E_EXP + tid] = running;
                running += c;
            }
            runBase[tid] = running;
        }
        __syncthreads();
        g_loc[s] = warpCnt[w * E_EXP + e] + rank;
        __syncthreads();
    }
    if (tid < E_EXP) g_cnt[tid] = runBase[tid];
}

// ---------------- aux loss (deterministic fixed-order reduction) ----------------
__global__ void aux_kernel(float* laux_out) {
    const int e = threadIdx.x;  // 64 threads
    float gs = 0.0f;
    for (int p = 0; p < 512; p++) gs += g_partialGateSum[(size_t)p * E_EXP + e];
    float me = gs / (float)S_TOK;
    float ce = (float)g_cnt[e] / (float)S_TOK;
    __shared__ float red[E_EXP];
    red[e] = me * ce;
    __syncthreads();
#pragma unroll
    for (int off = 32; off; off >>= 1) {
        if (e < off) red[e] += red[e + off];
        __syncthreads();
    }
    // l_aux = mean_e(me*ce) * E*E = sum * E
    if (e == 0 && laux_out) laux_out[0] = red[0] * (float)E_EXP;
}

// ---------------- scatter combine + mask ----------------
__global__ void scatter_kernel(float* __restrict__ combine, float* __restrict__ maskp) {
    const int s = blockIdx.x * blockDim.x + threadIdx.x;
    if (s >= S_TOK) return;
    const int loc = g_loc[s];
    if (loc >= CAP) return;  // dropped: row stays zero
    const int e = g_idx[s];
    const size_t off = (size_t)s * (E_EXP * CAP) + (size_t)e * CAP + loc;
    combine[off] = g_gate1[s];
    if (maskp) maskp[off] = 1.0f;
}

// ---------------- launch ----------------
extern "C" void kernel_launch(void* const* d_in, const int* in_sizes, int n_in,
                              void* d_out, int out_size) {
    const float* x  = (const float*)d_in[0];   // [S, D]
    const float* wg = (const float*)d_in[1];   // [E, D]
    float* out = (float*)d_out;

    const long long SEC = (long long)S_TOK * E_EXP * CAP;  // 67,108,864
    float* lauxp   = nullptr;
    float* combine = out;
    float* maskp   = nullptr;
    if ((long long)out_size >= 1 + 2 * SEC) {          // [l_aux, combine, mask]
        lauxp = out; combine = out + 1; maskp = out + 1 + SEC;
    } else if ((long long)out_size == 1 + SEC) {       // [l_aux, combine]
        lauxp = out; combine = out + 1;
    }                                                   // else: combine only

    cudaMemsetAsync(d_out, 0, (size_t)out_size * sizeof(float));

    gemm_kernel<<<S_TOK / BM, 128>>>(x, wg);
    softmax_kernel<<<64, 256>>>();
    scan_kernel<<<1, 1024>>>();
    aux_kernel<<<1, 64>>>(lauxp);
    scatter_kernel<<<(S_TOK + 255) / 256, 256>>>(combine, maskp);
}

// round 2
// speedup vs baseline: 1.0570x; 1.0570x over previous
#include <cuda_runtime.h>
#include <cstdint>

#define S_TOK 8192
#define D_DIM 2048
#define E_EXP 64
#define CAP   128

// ---------------- scratch ----------------
__device__ int   g_idx[S_TOK];
__device__ float g_gate1[S_TOK];
__device__ int   g_loc[S_TOK];
__device__ float g_partialGateSum[128 * E_EXP];   // per-gemm-block softmax sums

// ---------------- fused GEMM + softmax epilogue + output zeroing ----------------
// Blocks 0..127: 64-token x 64-expert GEMM tile (256 threads, 4x4 thread tile),
//                then softmax+argmax epilogue for their 64 tokens.
// Blocks 128.. : zero-fill d_out (runs concurrently, uses idle DRAM BW).
#define GEMM_BLOCKS 128
#define ZERO_BLOCKS 1792
#define BM 64
#define BN 64
#define BK 32
#define SROW 68   // padded row stride (272B, 16B-aligned)

__global__ void __launch_bounds__(256) fused_kernel(const float* __restrict__ x,
                                                    const float* __restrict__ wg,
                                                    float* __restrict__ out,
                                                    long long out_elems) {
    // ---------- zero role ----------
    if (blockIdx.x >= GEMM_BLOCKS) {
        const long long zb = blockIdx.x - GEMM_BLOCKS;
        const long long total4 = out_elems >> 2;
        float4* o4 = (float4*)out;
        const float4 z = make_float4(0.f, 0.f, 0.f, 0.f);
        const long long stride = (long long)ZERO_BLOCKS * 256;
        for (long long i = zb * 256 + threadIdx.x; i < total4; i += stride) o4[i] = z;
        if (zb == 0 && threadIdx.x == 0)
            for (long long i = total4 * 4; i < out_elems; i++) out[i] = 0.f;
        return;
    }

    // ---------- GEMM role ----------
    __shared__ float sm[2 * BK * SROW];       // Xs[32][68] | Ws[32][68]; reused as Ls[64][68]
    __shared__ float pg[8 * E_EXP];
    float (*Xs)[SROW] = (float(*)[SROW])sm;
    float (*Ws)[SROW] = (float(*)[SROW])(sm + BK * SROW);
    float (*Ls)[SROW] = (float(*)[SROW])sm;

    const int tid = threadIdx.x;
    const int m0  = blockIdx.x * BM;
    const int tx  = tid & 15;    // expert group: tx*4..tx*4+3
    const int ty  = tid >> 4;    // token  group: ty*4..ty*4+3

    int rowi[2], c4i[2];
#pragma unroll
    for (int i = 0; i < 2; i++) {
        int f = tid + i * 256;   // 512 float4 per 64x32 tile
        rowi[i] = f >> 3;
        c4i[i]  = f & 7;
    }

    float4 xr[2], wr[2];
#pragma unroll
    for (int i = 0; i < 2; i++) {
        xr[i] = *(const float4*)(x  + (size_t)(m0 + rowi[i]) * D_DIM + c4i[i] * 4);
        wr[i] = *(const float4*)(wg + (size_t)rowi[i] * D_DIM + c4i[i] * 4);
    }

    float acc[4][4];
#pragma unroll
    for (int i = 0; i < 4; i++)
#pragma unroll
        for (int j = 0; j < 4; j++) acc[i][j] = 0.0f;

    const int NT = D_DIM / BK;
    for (int kt = 0; kt < NT; kt++) {
#pragma unroll
        for (int i = 0; i < 2; i++) {
            int c = c4i[i] * 4, r = rowi[i];
            Xs[c + 0][r] = xr[i].x; Xs[c + 1][r] = xr[i].y;
            Xs[c + 2][r] = xr[i].z; Xs[c + 3][r] = xr[i].w;
            Ws[c + 0][r] = wr[i].x; Ws[c + 1][r] = wr[i].y;
            Ws[c + 2][r] = wr[i].z; Ws[c + 3][r] = wr[i].w;
        }
        __syncthreads();

        if (kt + 1 < NT) {
            int k0 = (kt + 1) * BK;
#pragma unroll
            for (int i = 0; i < 2; i++) {
                xr[i] = *(const float4*)(x  + (size_t)(m0 + rowi[i]) * D_DIM + k0 + c4i[i] * 4);
                wr[i] = *(const float4*)(wg + (size_t)rowi[i] * D_DIM + k0 + c4i[i] * 4);
            }
        }

#pragma unroll
        for (int k = 0; k < BK; k++) {
            float4 a4 = *(const float4*)&Xs[k][ty * 4];
            float4 b4 = *(const float4*)&Ws[k][tx * 4];
            float a[4] = {a4.x, a4.y, a4.z, a4.w};
            float b[4] = {b4.x, b4.y, b4.z, b4.w};
#pragma unroll
            for (int i = 0; i < 4; i++)
#pragma unroll
                for (int j = 0; j < 4; j++) acc[i][j] = fmaf(a[i], b[j], acc[i][j]);
        }
        __syncthreads();
    }

    // ---------- softmax epilogue ----------
    // stash logits tile into smem (reuse Xs/Ws region as Ls[64][68])
#pragma unroll
    for (int i = 0; i < 4; i++)
        *(float4*)&Ls[ty * 4 + i][tx * 4] = make_float4(acc[i][0], acc[i][1], acc[i][2], acc[i][3]);
    __syncthreads();

    const int wpid = tid >> 5, lane = tid & 31;
    float pa0 = 0.0f, pa1 = 0.0f;
#pragma unroll
    for (int t = 0; t < 8; t++) {
        const int row = wpid * 8 + t;
        float l0 = Ls[row][lane];
        float l1 = Ls[row][lane + 32];
        // argmax, first-occurrence tie-break (matches jnp.argmax)
        float mv; int mi;
        if (l0 >= l1) { mv = l0; mi = lane; } else { mv = l1; mi = lane + 32; }
#pragma unroll
        for (int off = 16; off; off >>= 1) {
            float ov = __shfl_down_sync(0xffffffffu, mv, off);
            int   oi = __shfl_down_sync(0xffffffffu, mi, off);
            if (ov > mv || (ov == mv && oi < mi)) { mv = ov; mi = oi; }
        }
        mv = __shfl_sync(0xffffffffu, mv, 0);
        mi = __shfl_sync(0xffffffffu, mi, 0);

        float e0 = expf(l0 - mv), e1 = expf(l1 - mv);
        float sum = e0 + e1;
#pragma unroll
        for (int off = 16; off; off >>= 1) sum += __shfl_down_sync(0xffffffffu, sum, off);
        sum = __shfl_sync(0xffffffffu, sum, 0);
        float inv = 1.0f / sum;

        pa0 += e0 * inv;
        pa1 += e1 * inv;
        if (lane == 0) { g_idx[m0 + row] = mi; g_gate1[m0 + row] = inv; }
    }
    pg[wpid * E_EXP + lane]      = pa0;
    pg[wpid * E_EXP + lane + 32] = pa1;
    __syncthreads();
    if (tid < E_EXP) {
        float s = 0.0f;
#pragma unroll
        for (int w8 = 0; w8 < 8; w8++) s += pg[w8 * E_EXP + tid];
        g_partialGateSum[(size_t)blockIdx.x * E_EXP + tid] = s;
    }
}

// ---------------- ordered per-expert rank + aux loss (single block, fused) ----------------
__global__ void __launch_bounds__(1024) scan_aux_kernel(float* __restrict__ out) {
    __shared__ int   hist[32 * E_EXP];
    __shared__ float red[16 * E_EXP];
    __shared__ int   cntS[E_EXP];
    __shared__ float vals[E_EXP];

    const int tid = threadIdx.x, lane = tid & 31, w = tid >> 5;
    hist[tid] = 0; hist[tid + 1024] = 0;
    __syncthreads();

    // phase 1: warp-local ordered ranks over 256 contiguous tokens
    int eArr[8], locArr[8];
    const int base = w * 256;
#pragma unroll
    for (int g = 0; g < 8; g++) {
        const int s = base + g * 32 + lane;
        const int e = g_idx[s];
        unsigned mask = __match_any_sync(0xffffffffu, e);
        int rank = __popc(mask & ((1u << lane) - 1u));
        int bcnt = hist[w * E_EXP + e];
        eArr[g] = e; locArr[g] = bcnt + rank;
        __syncwarp();
        if (lane == __ffs(mask) - 1) hist[w * E_EXP + e] = bcnt + __popc(mask);
        __syncwarp();
    }
    __syncthreads();

    // phase 2: exclusive prefix across warps, per expert
    if (tid < E_EXP) {
        int running = 0;
        for (int ww = 0; ww < 32; ww++) {
            int c = hist[ww * E_EXP + tid];
            hist[ww * E_EXP + tid] = running;
            running += c;
        }
        cntS[tid] = running;
    }
    __syncthreads();

    // phase 3: final locations
#pragma unroll
    for (int g = 0; g < 8; g++)
        g_loc[base + g * 32 + lane] = hist[w * E_EXP + eArr[g]] + locArr[g];

    // phase 4: aux loss (deterministic fixed-order)
    {
        const int e = tid & 63, r = tid >> 6;  // 16 slices x 64 experts
        float sum = 0.0f;
        for (int p = r * 8; p < r * 8 + 8; p++) sum += g_partialGateSum[(size_t)p * E_EXP + e];
        red[(size_t)r * E_EXP + e] = sum;
    }
    __syncthreads();
    if (tid < E_EXP) {
        float me = 0.0f;
#pragma unroll
        for (int r = 0; r < 16; r++) me += red[r * E_EXP + tid];
        me /= (float)S_TOK;
        float ce = (float)cntS[tid] / (float)S_TOK;
        vals[tid] = me * ce;
    }
    __syncthreads();
    if (tid == 0 && out) {
        float a = 0.0f;
        for (int e = 0; e < E_EXP; e++) a += vals[e];
        out[0] = a * (float)E_EXP;   // mean * E*E == sum * E
    }
}

// ---------------- scatter combine + mask ----------------
__global__ void scatter_kernel(float* __restrict__ combine, float* __restrict__ maskp) {
    const int s = blockIdx.x * blockDim.x + threadIdx.x;
    if (s >= S_TOK) return;
    const int loc = g_loc[s];
    if (loc >= CAP) return;   // dropped: row stays zero
    const int e = g_idx[s];
    const size_t off = (size_t)s * (E_EXP * CAP) + (size_t)e * CAP + loc;
    combine[off] = g_gate1[s];
    if (maskp) maskp[off] = 1.0f;
}

// ---------------- launch ----------------
extern "C" void kernel_launch(void* const* d_in, const int* in_sizes, int n_in,
                              void* d_out, int out_size) {
    const float* x  = (const float*)d_in[0];   // [S, D]
    const float* wg = (const float*)d_in[1];   // [E, D]
    float* out = (float*)d_out;

    const long long SEC = (long long)S_TOK * E_EXP * CAP;  // 67,108,864
    float* lauxp   = nullptr;
    float* combine = out;
    float* maskp   = nullptr;
    if ((long long)out_size >= 1 + 2 * SEC) {          // [l_aux, combine, mask]
        lauxp = out; combine = out + 1; maskp = out + 1 + SEC;
    } else if ((long long)out_size == 1 + SEC) {       // [l_aux, combine]
        lauxp = out; combine = out + 1;
    }

    fused_kernel<<<GEMM_BLOCKS + ZERO_BLOCKS, 256>>>(x, wg, out, (long long)out_size);
    scan_aux_kernel<<<1, 1024>>>(lauxp);
    scatter_kernel<<<(S_TOK + 255) / 256, 256>>>(combine, maskp);
}